// round 14
// baseline (speedup 1.0000x reference)
#include <cuda_runtime.h>
#include <cuda_bf16.h>
#include <mma.h>
#include <cstdint>
#include <cstddef>

using namespace nvcuda;

#define BB 64
#define TT 512
#define EE 300
#define UU 1024
#define G3 3072
// ---- scan tiling: 32 m-tiles (96 rows = 3 gates x 32 u) x 4 k-slices ----
#define NMT 32
#define NSLC 4
#define NCTA 128
#define KSL 768            // K' per slice
#define NTH 384            // 12 warps
#define A_PITCH 776        // 768 + 8
#define A_BYTES (96 * A_PITCH * 2)        // 148992
#define B_PITCH 136        // 128 + 8
#define BCH_BYTES (64 * B_PITCH * 2)      // 17408
#define NBST 3
#define PS_LD 100          // col-major staging ld (96 rows + pad)
#define PS_BYTES (PS_LD * 64 * 4)         // 25600
#define SMEM_BYTES (A_BYTES + NBST * BCH_BYTES + PS_BYTES)  // 226816

// Input-GEMM (bf16-split WMMA) geometry
#define IEK 304
#define IKP (3 * IEK)      // 912
#define IKC 48
#define INKC (IKP / IKC)   // 19
#define IAP 56
#define IBP 72
#define IPSP 72

// ---- static device scratch ----
__device__ float g_xp[(size_t)3 * TT * BB * UU];                       // [gate][t][b][u]
__device__ __align__(16) __nv_bfloat16 g_Apack[(size_t)NCTA * 96 * A_PITCH];
__device__ __align__(16) __nv_bfloat16 g_Bcat[(size_t)BB * G3];        // [b][hhi|hlo|hhi]
__device__ float g_Pp[(size_t)NCTA * 64 * 96];                         // [cta][b][row]
__device__ __align__(16) __nv_bfloat16 g_Acat[(size_t)BB * TT * IKP];
__device__ __align__(16) __nv_bfloat16 g_Wcat[(size_t)IKP * G3];
__device__ unsigned g_bar;
__device__ unsigned g_gbar[NMT * 64];     // 256B-strided group counters

__global__ void init_bar_kernel() {
    int i = blockIdx.x * 256 + threadIdx.x;
    if (i == 0) g_bar = 0u;
    if (i < NMT * 64) g_gbar[i] = 0u;
}

__device__ __forceinline__ void cp16(void* dst, const void* src) {
    unsigned d = (unsigned)__cvta_generic_to_shared(dst);
    asm volatile("cp.async.cg.shared.global [%0], [%1], 16;\n" :: "r"(d), "l"(src));
}
__device__ __forceinline__ void cpa_commit() {
    asm volatile("cp.async.commit_group;\n");
}

// Proven single atomic-counter grid barrier.
__device__ __forceinline__ void gbar_sync(unsigned target) {
    __syncthreads();
    if (threadIdx.x == 0) {
        __threadfence();
        atomicAdd(&g_bar, 1u);
        while (*(volatile unsigned*)&g_bar < target) { }
        __threadfence();
    }
    __syncthreads();
}

// Group barrier (4 CTAs sharing one m-tile).
__device__ __forceinline__ void group_sync(int mt, unsigned target) {
    __syncthreads();
    if (threadIdx.x == 0) {
        __threadfence();
        atomicAdd(&g_gbar[mt * 64], 1u);
        while (*(volatile unsigned*)&g_gbar[mt * 64] < target) { }
        __threadfence();
    }
    __syncthreads();
}

// ---------------------------------------------------------------------------
// Pack A': cta = mt*4 + sl; row r = g*32 + uu (u = mt*32+uu, m = g*1024+u);
// col j in [0,768): k' = sl*768 + j, region = k'>>10, k = k'&1023.
// region 0,1 -> Rhi[k][m]; region 2 -> Rlo[k][m].
// ---------------------------------------------------------------------------
__global__ void pack_A_kernel(const float* __restrict__ Rk) {
    size_t idx = (size_t)blockIdx.x * 256 + threadIdx.x;
    if (idx >= (size_t)G3 * G3) return;
    int m  = (int)(idx / G3);
    int kp = (int)(idx - (size_t)m * G3);
    int g  = m >> 10;
    int u  = m & 1023;
    int mt = u >> 5;
    int uu = u & 31;
    int sl = kp / KSL;
    int j  = kp - sl * KSL;
    int region = kp >> 10;
    int k = kp & 1023;
    float v = Rk[(size_t)k * G3 + m];
    __nv_bfloat16 hi = __float2bfloat16(v);
    __nv_bfloat16 wv = (region == 2) ? __float2bfloat16(v - __bfloat162float(hi)) : hi;
    g_Apack[(size_t)(mt * NSLC + sl) * (96 * A_PITCH) + (g * 32 + uu) * A_PITCH + j] = wv;
}

// ---------------------------------------------------------------------------
__global__ void prep_B_kernel(const float* __restrict__ hidden0) {
    int idx = blockIdx.x * 256 + threadIdx.x;
    if (idx >= BB * UU) return;
    int b = idx >> 10, u = idx & 1023;
    float v = hidden0[idx];
    __nv_bfloat16 hi = __float2bfloat16(v);
    __nv_bfloat16 lo = __float2bfloat16(v - __bfloat162float(hi));
    g_Bcat[(size_t)b * G3 + u] = hi;
    g_Bcat[(size_t)b * G3 + 1024 + u] = lo;
    g_Bcat[(size_t)b * G3 + 2048 + u] = hi;
}

// ---------------------------------------------------------------------------
__global__ void pack_W_kernel(const float* __restrict__ W) {
    size_t idx = (size_t)blockIdx.x * 256 + threadIdx.x;
    if (idx >= (size_t)IKP * G3) return;
    int kp = (int)(idx / G3);
    int n  = (int)(idx - (size_t)kp * G3);
    int region = (kp >= 2 * IEK) ? 2 : (kp >= IEK ? 1 : 0);
    int e = kp - region * IEK;
    float v = (e < EE) ? W[(size_t)e * G3 + n] : 0.f;
    __nv_bfloat16 hi = __float2bfloat16(v);
    __nv_bfloat16 wv = (region == 2) ? __float2bfloat16(v - __bfloat162float(hi)) : hi;
    g_Wcat[idx] = wv;
}

__global__ void pack_Acat_kernel(const int* __restrict__ x,
                                 const float* __restrict__ emb) {
    int m = blockIdx.x * 8 + (threadIdx.x >> 5);
    int lane = threadIdx.x & 31;
    int tok = x[m];
    const float* erow = emb + (size_t)tok * EE;
    __nv_bfloat16* arow = g_Acat + (size_t)m * IKP;
    for (int c = lane; c < IEK; c += 32) {
        float v = (c < EE) ? erow[c] : 0.f;
        __nv_bfloat16 hi = __float2bfloat16(v);
        __nv_bfloat16 lo = __float2bfloat16(v - __bfloat162float(hi));
        arow[c] = hi;
        arow[IEK + c] = lo;
        arow[2 * IEK + c] = hi;
    }
}

// ---------------------------------------------------------------------------
// Input GEMM (WMMA bf16-split) — unchanged from R13.
// ---------------------------------------------------------------------------
__global__ void __launch_bounds__(256, 2)
input_wmma_kernel(const float* __restrict__ bias0) {
    __shared__ __align__(16) unsigned char smbuf[2 * 128 * IAP * 2 + 2 * IKC * IBP * 2];
    __nv_bfloat16* Asm = (__nv_bfloat16*)smbuf;
    __nv_bfloat16* Bsm = (__nv_bfloat16*)(smbuf + 2 * 128 * IAP * 2);
    float* Ps = (float*)smbuf;

    int tid = threadIdx.x;
    int n0 = blockIdx.x * 64;
    int m0 = blockIdx.y * 128;
    int w  = tid >> 5;
    int wm = w & 3;
    int wn = w >> 2;

    auto load_stage = [&](int st, int c) {
        int k0 = c * IKC;
#pragma unroll
        for (int i = 0; i < 3; i++) {
            int lin = tid + i * 256;
            int row = lin / 6, seg = lin % 6;
            cp16(Asm + (size_t)st * 128 * IAP + row * IAP + seg * 8,
                 g_Acat + (size_t)(m0 + row) * IKP + k0 + seg * 8);
        }
#pragma unroll
        for (int i = 0; i < 2; i++) {
            int lin = tid + i * 256;
            if (lin < 384) {
                int row = lin >> 3, seg = lin & 7;
                cp16(Bsm + (size_t)st * IKC * IBP + row * IBP + seg * 8,
                     g_Wcat + (size_t)(k0 + row) * G3 + n0 + seg * 8);
            }
        }
        cpa_commit();
    };

    load_stage(0, 0);
    load_stage(1, 1);

    wmma::fragment<wmma::accumulator, 16, 16, 16, float> acc[2][2];
#pragma unroll
    for (int i = 0; i < 2; i++)
#pragma unroll
        for (int j = 0; j < 2; j++) wmma::fill_fragment(acc[i][j], 0.0f);

    for (int c = 0; c < INKC; c++) {
        if (c + 1 < INKC) asm volatile("cp.async.wait_group 1;\n");
        else              asm volatile("cp.async.wait_group 0;\n");
        __syncthreads();

        int st = c & 1;
        const __nv_bfloat16* Ab = Asm + (size_t)st * 128 * IAP + (size_t)(wm * 32) * IAP;
        const __nv_bfloat16* Bb = Bsm + (size_t)st * IKC * IBP + wn * 32;
#pragma unroll
        for (int kk = 0; kk < 3; kk++) {
            wmma::fragment<wmma::matrix_a, 16, 16, 16, __nv_bfloat16, wmma::row_major> af[2];
            wmma::fragment<wmma::matrix_b, 16, 16, 16, __nv_bfloat16, wmma::row_major> bf[2];
            wmma::load_matrix_sync(af[0], Ab + kk * 16, IAP);
            wmma::load_matrix_sync(af[1], Ab + (size_t)16 * IAP + kk * 16, IAP);
            wmma::load_matrix_sync(bf[0], Bb + (size_t)(kk * 16) * IBP, IBP);
            wmma::load_matrix_sync(bf[1], Bb + (size_t)(kk * 16) * IBP + 16, IBP);
            wmma::mma_sync(acc[0][0], af[0], bf[0], acc[0][0]);
            wmma::mma_sync(acc[0][1], af[0], bf[1], acc[0][1]);
            wmma::mma_sync(acc[1][0], af[1], bf[0], acc[1][0]);
            wmma::mma_sync(acc[1][1], af[1], bf[1], acc[1][1]);
        }
        __syncthreads();
        if (c + 2 < INKC) load_stage(st, c + 2);
    }

    __syncthreads();
#pragma unroll
    for (int i = 0; i < 2; i++)
#pragma unroll
        for (int j = 0; j < 2; j++)
            wmma::store_matrix_sync(Ps + (size_t)(wm * 32 + i * 16) * IPSP + wn * 32 + j * 16,
                                    acc[i][j], IPSP, wmma::mem_row_major);
    __syncthreads();

    int g = n0 >> 10;
    int ub = n0 & 1023;
#pragma unroll
    for (int i = 0; i < 8; i++) {
        int lin = tid + i * 256;
        int row = lin >> 4;
        int q   = lin & 15;
        float4 v = *(const float4*)&Ps[row * IPSP + q * 4];
        float4 bv = *(const float4*)&bias0[n0 + q * 4];
        v.x += bv.x; v.y += bv.y; v.z += bv.z; v.w += bv.w;
        int m = m0 + row;
        int b = m >> 9, t = m & 511;
        *(float4*)&g_xp[(((size_t)g * TT + t) * BB + b) * UU + ub + q * 4] = v;
    }
}

// ---------------------------------------------------------------------------
// Persistent WMMA GRU scan, gate-aligned tiling. 128 CTAs x 384 threads.
// cta = mt*4 + sl. A slice (96 rows = 3 gates x 32 u, K=768) smem-resident.
// Per step: 3-stage B ring (6 chunks), 96 wmma/warp, partials staged col-major
// then coalesced to g_Pp[cta][b][row], GROUP barrier (4 CTAs), local epilogue
// (16 b x 32 u per CTA), ONE global barrier.
// ---------------------------------------------------------------------------
__global__ void __launch_bounds__(NTH, 1)
gru_wmma_kernel(const float* __restrict__ hidden0,
                const float* __restrict__ bias,
                float* __restrict__ out,
                int write_state) {
    extern __shared__ unsigned char sm[];
    __nv_bfloat16* Asm = (__nv_bfloat16*)sm;
    unsigned char* Bsm = sm + A_BYTES;
    float* Ps = (float*)(sm + A_BYTES + NBST * BCH_BYTES);

    int tid = threadIdx.x;
    int cta = blockIdx.x;
    int mt = cta >> 2;       // m-tile (0..31)
    int sl = cta & 3;        // k-slice (0..3)
    int w  = tid >> 5;
    int wm = w % 3;          // 32-row group (0..2)
    int wn = w / 3;          // 16-col group (0..3)

    // Load resident A slice once.
    {
        const unsigned char* src = (const unsigned char*)g_Apack + (size_t)cta * A_BYTES;
        for (int i = tid; i < A_BYTES / 16; i += NTH)
            cp16(sm + (size_t)i * 16, src + (size_t)i * 16);
        cpa_commit();
        asm volatile("cp.async.wait_group 0;\n");
    }
    __syncthreads();

    int kbase = sl * KSL;    // column window in Bcat

    // Epilogue: this CTA covers b in [sl*16, sl*16+16), u in [mt*32, mt*32+32).
    // 512 scalar units over 2 passes of 384 threads.
    int eb[2], eu[2];
    bool act[2];
    float bz[2], br[2], bh[2], hp[2];
#pragma unroll
    for (int p = 0; p < 2; p++) {
        int unit = p * NTH + tid;
        act[p] = (unit < 512);
        int uu = unit & 31, bl = (unit >> 5) & 15;
        eb[p] = sl * 16 + bl;
        eu[p] = mt * 32 + uu;
        if (act[p]) {
            bz[p] = bias[G3 + eu[p]];
            br[p] = bias[G3 + UU + eu[p]];
            bh[p] = bias[G3 + 2 * UU + eu[p]];
            hp[p] = hidden0[(size_t)eb[p] * UU + eu[p]];
        } else { bz[p]=br[p]=bh[p]=hp[p]=0.f; }
    }

    const __nv_bfloat16* Aw = Asm + (size_t)(wm * 32) * A_PITCH;
    float* gpp = g_Pp + (size_t)cta * 64 * 96;    // [b][row]

    unsigned tgt = 0;
    for (int t = 0; t < TT; t++) {
        // Prologue: issue chunks 0,1,2 into ring buffers 0,1,2.
#pragma unroll
        for (int kc = 0; kc < 3; kc++) {
#pragma unroll
            for (int i = 0; i < 3; i++) {
                int lin = tid + i * NTH;
                if (lin < 1024) {
                    int row = lin >> 4, seg = lin & 15;
                    cp16(Bsm + kc * BCH_BYTES + row * (B_PITCH * 2) + seg * 16,
                         (const unsigned char*)(g_Bcat + (size_t)row * G3 + kbase + kc * 128)
                         + seg * 16);
                }
            }
            cpa_commit();
        }

        wmma::fragment<wmma::accumulator, 16, 16, 16, float> acc[2];
        wmma::fill_fragment(acc[0], 0.0f);
        wmma::fill_fragment(acc[1], 0.0f);

#pragma unroll
        for (int c = 0; c < 6; c++) {
            // pending allowed: 2,1,1,1,1,0
            if      (c == 0) asm volatile("cp.async.wait_group 2;\n");
            else if (c == 5) asm volatile("cp.async.wait_group 0;\n");
            else             asm volatile("cp.async.wait_group 1;\n");
            __syncthreads();

            // Refill: chunk c+2 into buffer (c+2)%3 (held chunk c-1, consumed).
            if (c >= 1 && c + 2 <= 5) {
                int nc = c + 2;
                int buf = nc % 3;
#pragma unroll
                for (int i = 0; i < 3; i++) {
                    int lin = tid + i * NTH;
                    if (lin < 1024) {
                        int row = lin >> 4, seg = lin & 15;
                        cp16(Bsm + buf * BCH_BYTES + row * (B_PITCH * 2) + seg * 16,
                             (const unsigned char*)(g_Bcat + (size_t)row * G3 + kbase + nc * 128)
                             + seg * 16);
                    }
                }
                cpa_commit();
            }

            const __nv_bfloat16* Bb = (const __nv_bfloat16*)(Bsm + (c % 3) * BCH_BYTES);
#pragma unroll
            for (int kk = 0; kk < 8; kk++) {
                int j = c * 128 + kk * 16;
                wmma::fragment<wmma::matrix_a, 16, 16, 16, __nv_bfloat16, wmma::row_major> af[2];
                wmma::fragment<wmma::matrix_b, 16, 16, 16, __nv_bfloat16, wmma::col_major> bf;
                wmma::load_matrix_sync(af[0], Aw + j, A_PITCH);
                wmma::load_matrix_sync(af[1], Aw + (size_t)16 * A_PITCH + j, A_PITCH);
                wmma::load_matrix_sync(bf, Bb + (size_t)(wn * 16) * B_PITCH + kk * 16, B_PITCH);
                wmma::mma_sync(acc[0], af[0], bf, acc[0]);
                wmma::mma_sync(acc[1], af[1], bf, acc[1]);
            }
        }
        __syncthreads();

        // Stage partials col-major: element (row, b) at Ps[row + b*PS_LD].
#pragma unroll
        for (int i = 0; i < 2; i++)
            wmma::store_matrix_sync(Ps + (wm * 32 + i * 16) + (size_t)(wn * 16) * PS_LD,
                                    acc[i], PS_LD, wmma::mem_col_major);

        // Prefetch xp (hides under staging + group barrier).
        float xz[2], xr[2], xh[2];
#pragma unroll
        for (int p = 0; p < 2; p++) {
            if (act[p]) {
                xz[p] = g_xp[(((size_t)0 * TT + t) * BB + eb[p]) * UU + eu[p]];
                xr[p] = g_xp[(((size_t)1 * TT + t) * BB + eb[p]) * UU + eu[p]];
                xh[p] = g_xp[(((size_t)2 * TT + t) * BB + eb[p]) * UU + eu[p]];
            } else { xz[p]=xr[p]=xh[p]=0.f; }
        }
        __syncthreads();

        // Coalesced copy staging -> g_Pp[cta][b][row] (384B runs per b).
#pragma unroll
        for (int i = 0; i < 4; i++) {
            int lin = tid + i * NTH;          // 0..1535
            int b = lin / 24;
            int r4 = lin - b * 24;            // float4 index over 96 rows
            float4 v = *(const float4*)&Ps[r4 * 4 + b * PS_LD];
            *(float4*)&gpp[b * 96 + r4 * 4] = v;
        }

        // GROUP barrier: 4 CTAs of this m-tile.
        group_sync(mt, 4u * (t + 1));

        // Local epilogue: sum 4 slices x 3 gates from group partials.
#pragma unroll
        for (int p = 0; p < 2; p++) {
            if (!act[p]) continue;
            int unit = p * NTH + tid;
            int uu = unit & 31;
            int b = eb[p];
            float sz = 0.f, sr = 0.f, sh = 0.f;
#pragma unroll
            for (int s2 = 0; s2 < NSLC; s2++) {
                const float* pb = g_Pp + (size_t)(mt * NSLC + s2) * 64 * 96 + b * 96;
                sz += __ldcg(pb + uu);
                sr += __ldcg(pb + 32 + uu);
                sh += __ldcg(pb + 64 + uu);
            }
            float z  = __fdividef(1.f, 1.f + __expf(-(xz[p] + sz + bz[p])));
            float rg = __fdividef(1.f, 1.f + __expf(-(xr[p] + sr + br[p])));
            float ta = xh[p] + rg * (sh + bh[p]);
            float hh = 1.f - __fdividef(2.f, __expf(2.f * ta) + 1.f);
            float hn = z * hp[p] + (1.f - z) * hh;
            hp[p] = hn;
            __nv_bfloat16 hi = __float2bfloat16(hn);
            __nv_bfloat16 lo = __float2bfloat16(hn - __bfloat162float(hi));
            // Bcat first (next-step GEMM waits on these).
            g_Bcat[(size_t)b * G3 + eu[p]] = hi;
            g_Bcat[(size_t)b * G3 + 1024 + eu[p]] = lo;
            g_Bcat[(size_t)b * G3 + 2048 + eu[p]] = hi;
            out[((size_t)b * TT + t) * UU + eu[p]] = hn;
            if (write_state && t == TT - 1)
                out[(size_t)BB * TT * UU + (size_t)b * UU + eu[p]] = hn;
        }

        // ONE global barrier per step (Bcat visibility for all CTAs).
        tgt += NCTA; gbar_sync(tgt);
    }
}

// ---------------------------------------------------------------------------
extern "C" void kernel_launch(void* const* d_in, const int* in_sizes, int n_in,
                              void* d_out, int out_size) {
    const int*   x      = (const int*)d_in[0];
    const float* hidden = (const float*)d_in[1];
    const float* emb    = (const float*)d_in[2];
    const float* W      = (const float*)d_in[3];
    const float* Rk     = (const float*)d_in[4];
    const float* bias   = (const float*)d_in[5];
    float* out = (float*)d_out;

    int write_state = (out_size >= BB * TT * UU + BB * UU) ? 1 : 0;

    static int attr_done = 0;
    if (!attr_done) {
        cudaFuncSetAttribute(gru_wmma_kernel,
                             cudaFuncAttributeMaxDynamicSharedMemorySize, SMEM_BYTES);
        attr_done = 1;
    }

    init_bar_kernel<<<9, 256>>>();

    size_t ae = (size_t)G3 * G3;
    pack_A_kernel<<<(unsigned)((ae + 255) / 256), 256>>>(Rk);
    prep_B_kernel<<<(BB * UU + 255) / 256, 256>>>(hidden);

    size_t we = (size_t)IKP * G3;
    pack_W_kernel<<<(unsigned)((we + 255) / 256), 256>>>(W);
    pack_Acat_kernel<<<(BB * TT) / 8, 256>>>(x, emb);

    dim3 gI(G3 / 64, (BB * TT) / 128);   // (48, 256)
    input_wmma_kernel<<<gI, 256>>>(bias);

    gru_wmma_kernel<<<NCTA, NTH, SMEM_BYTES>>>(hidden, bias, out, write_state);
}

// round 15
// speedup vs baseline: 1.1594x; 1.1594x over previous
#include <cuda_runtime.h>
#include <cuda_bf16.h>
#include <mma.h>
#include <cstdint>
#include <cstddef>

using namespace nvcuda;

#define BB 64
#define TT 512
#define EE 300
#define UU 1024
#define G3 3072
#define NCTA 144           // 24 m-tiles x 6 k-slices
#define NSL 6
#define KSL 512
#define A_PITCH 520        // 512 + 8 pad (conflict-free ldmatrix)
#define A_BYTES (128 * A_PITCH * 2)       // 133120
#define B_PITCH 264        // 256 + 8 pad (bf16 elements)
#define BCH_BYTES (64 * B_PITCH * 2)      // 33792
#define PS_LD 132                         // staging ldm (col-major, 128 rows + pad)
#define SMEM_BYTES (A_BYTES + 2 * BCH_BYTES)                 // 200704
#define NU2 (BB * (UU / 2))               // 32768 float2 epilogue units
#define UPC2 228                          // ceil(NU2 / NCTA)

// Input-GEMM (bf16-split WMMA) geometry — 128x128 tile
#define IEK 304            // padded E per region
#define IKP (3 * IEK)      // K' = 912
#define IKC 48             // K chunk
#define INKC (IKP / IKC)   // 19 chunks
#define IAP 56             // A smem pitch (bf16)
#define IBP 136            // B smem pitch (bf16), 128 + 8
#define IPSP 72            // output staging pitch (float), 64 cols + 8

// ---- static device scratch ----
__device__ float g_xp[(size_t)3 * TT * BB * UU];                     // [gate][t][b][u]
__device__ __align__(16) __nv_bfloat16 g_Apack[(size_t)NCTA * 128 * A_PITCH];
__device__ __align__(16) __nv_bfloat16 g_Bcat[(size_t)BB * G3];      // [b][hhi|hlo|hhi]
__device__ float g_Pp[(size_t)NSL * BB * G3];                        // [slice][b][m]
__device__ __align__(16) __nv_bfloat16 g_Acat[(size_t)BB * TT * IKP];  // gathered emb split
__device__ __align__(16) __nv_bfloat16 g_Wcat[(size_t)IKP * G3];       // kernel split
__device__ unsigned g_bar;

__global__ void init_bar_kernel() { g_bar = 0u; }

__device__ __forceinline__ void cp16(void* dst, const void* src) {
    unsigned d = (unsigned)__cvta_generic_to_shared(dst);
    asm volatile("cp.async.cg.shared.global [%0], [%1], 16;\n" :: "r"(d), "l"(src));
}
__device__ __forceinline__ void cpa_commit() {
    asm volatile("cp.async.commit_group;\n");
}
__device__ __forceinline__ unsigned packbf2(float a, float b) {
    __nv_bfloat16 ha = __float2bfloat16(a), hb = __float2bfloat16(b);
    unsigned short ua = *(unsigned short*)&ha, ub = *(unsigned short*)&hb;
    return (unsigned)ua | ((unsigned)ub << 16);
}

// Proven atomic-counter grid barrier (best measured across R7/R8/R12/R14).
__device__ __forceinline__ void gbar_sync(unsigned target) {
    __syncthreads();
    if (threadIdx.x == 0) {
        __threadfence();
        atomicAdd(&g_bar, 1u);
        while (*(volatile unsigned*)&g_bar < target) { }
        __threadfence();
    }
    __syncthreads();
}

// ---------------------------------------------------------------------------
// Pack A' slices for the scan GEMM. cta = mt*6 + s; slice s covers k'=s*512:
//   k'<1024: Rhi*hhi   1024..2047: Rhi*hlo   2048..3071: Rlo*hhi
// ---------------------------------------------------------------------------
__global__ void pack_A_kernel(const float* __restrict__ Rk) {
    size_t idx = (size_t)blockIdx.x * 256 + threadIdx.x;
    if (idx >= (size_t)G3 * G3) return;
    int m  = (int)(idx / G3);
    int kp = (int)(idx - (size_t)m * G3);
    int s = kp >> 9;
    int j = kp & 511;
    int k = ((s & 1) << 9) + j;
    int region = s >> 1;
    float v = Rk[(size_t)k * G3 + m];
    __nv_bfloat16 hi = __float2bfloat16(v);
    __nv_bfloat16 wv = (region == 2) ? __float2bfloat16(v - __bfloat162float(hi)) : hi;
    int mt = m >> 7, ml = m & 127;
    g_Apack[(size_t)(mt * NSL + s) * (128 * A_PITCH) + ml * A_PITCH + j] = wv;
}

// ---------------------------------------------------------------------------
__global__ void prep_B_kernel(const float* __restrict__ hidden0) {
    int idx = blockIdx.x * 256 + threadIdx.x;
    if (idx >= BB * UU) return;
    int b = idx >> 10, u = idx & 1023;
    float v = hidden0[idx];
    __nv_bfloat16 hi = __float2bfloat16(v);
    __nv_bfloat16 lo = __float2bfloat16(v - __bfloat162float(hi));
    g_Bcat[(size_t)b * G3 + u] = hi;
    g_Bcat[(size_t)b * G3 + 1024 + u] = lo;
    g_Bcat[(size_t)b * G3 + 2048 + u] = hi;
}

// ---------------------------------------------------------------------------
__global__ void pack_W_kernel(const float* __restrict__ W) {
    size_t idx = (size_t)blockIdx.x * 256 + threadIdx.x;
    if (idx >= (size_t)IKP * G3) return;
    int kp = (int)(idx / G3);
    int n  = (int)(idx - (size_t)kp * G3);
    int region = (kp >= 2 * IEK) ? 2 : (kp >= IEK ? 1 : 0);
    int e = kp - region * IEK;
    float v = (e < EE) ? W[(size_t)e * G3 + n] : 0.f;
    __nv_bfloat16 hi = __float2bfloat16(v);
    __nv_bfloat16 wv = (region == 2) ? __float2bfloat16(v - __bfloat162float(hi)) : hi;
    g_Wcat[idx] = wv;
}

__global__ void pack_Acat_kernel(const int* __restrict__ x,
                                 const float* __restrict__ emb) {
    int m = blockIdx.x * 8 + (threadIdx.x >> 5);
    int lane = threadIdx.x & 31;
    int tok = x[m];
    const float* erow = emb + (size_t)tok * EE;
    __nv_bfloat16* arow = g_Acat + (size_t)m * IKP;
    for (int c = lane; c < IEK; c += 32) {
        float v = (c < EE) ? erow[c] : 0.f;
        __nv_bfloat16 hi = __float2bfloat16(v);
        __nv_bfloat16 lo = __float2bfloat16(v - __bfloat162float(hi));
        arow[c] = hi;
        arow[IEK + c] = lo;
        arow[2 * IEK + c] = hi;
    }
}

// ---------------------------------------------------------------------------
// Input GEMM (WMMA bf16-split), 128m x 128n tile, 8 warps (32m x 64n each),
// K chunks of 48, 2-stage cp.async. Output staged per 64-col half.
// ---------------------------------------------------------------------------
__global__ void __launch_bounds__(256, 2)
input_wmma_kernel(const float* __restrict__ bias0) {
    __shared__ __align__(16) unsigned char smbuf[2 * 128 * IAP * 2 + 2 * IKC * IBP * 2];
    __nv_bfloat16* Asm = (__nv_bfloat16*)smbuf;                       // [2][128*IAP]
    __nv_bfloat16* Bsm = (__nv_bfloat16*)(smbuf + 2 * 128 * IAP * 2); // [2][IKC*IBP]
    float* Ps = (float*)smbuf;   // alias after GEMM: 128*IPSP*4 = 36864 <= 54784

    int tid = threadIdx.x;
    int n0 = blockIdx.x * 128;
    int m0 = blockIdx.y * 128;
    int w  = tid >> 5;
    int wm = w & 3;           // 32-row group
    int wn = w >> 2;          // 64-col group (0..1)

    auto load_stage = [&](int st, int c) {
        int k0 = c * IKC;
#pragma unroll
        for (int i = 0; i < 3; i++) {             // A: 768 x 16B
            int lin = tid + i * 256;
            int row = lin / 6, seg = lin % 6;
            cp16(Asm + (size_t)st * 128 * IAP + row * IAP + seg * 8,
                 g_Acat + (size_t)(m0 + row) * IKP + k0 + seg * 8);
        }
#pragma unroll
        for (int i = 0; i < 3; i++) {             // B: 48x128 = 768 x 16B
            int lin = tid + i * 256;
            int row = lin >> 4, seg = lin & 15;
            cp16(Bsm + (size_t)st * IKC * IBP + row * IBP + seg * 8,
                 g_Wcat + (size_t)(k0 + row) * G3 + n0 + seg * 8);
        }
        cpa_commit();
    };

    load_stage(0, 0);
    load_stage(1, 1);

    wmma::fragment<wmma::accumulator, 16, 16, 16, float> acc[2][4];
#pragma unroll
    for (int i = 0; i < 2; i++)
#pragma unroll
        for (int j = 0; j < 4; j++) wmma::fill_fragment(acc[i][j], 0.0f);

    for (int c = 0; c < INKC; c++) {
        if (c + 1 < INKC) asm volatile("cp.async.wait_group 1;\n");
        else              asm volatile("cp.async.wait_group 0;\n");
        __syncthreads();

        int st = c & 1;
        const __nv_bfloat16* Ab = Asm + (size_t)st * 128 * IAP + (size_t)(wm * 32) * IAP;
        const __nv_bfloat16* Bb = Bsm + (size_t)st * IKC * IBP + wn * 64;
#pragma unroll
        for (int kk = 0; kk < 3; kk++) {
            wmma::fragment<wmma::matrix_a, 16, 16, 16, __nv_bfloat16, wmma::row_major> af[2];
            wmma::fragment<wmma::matrix_b, 16, 16, 16, __nv_bfloat16, wmma::row_major> bf[4];
            wmma::load_matrix_sync(af[0], Ab + kk * 16, IAP);
            wmma::load_matrix_sync(af[1], Ab + (size_t)16 * IAP + kk * 16, IAP);
#pragma unroll
            for (int j = 0; j < 4; j++)
                wmma::load_matrix_sync(bf[j], Bb + (size_t)(kk * 16) * IBP + j * 16, IBP);
#pragma unroll
            for (int j = 0; j < 4; j++) {
                wmma::mma_sync(acc[0][j], af[0], bf[j], acc[0][j]);
                wmma::mma_sync(acc[1][j], af[1], bf[j], acc[1][j]);
            }
        }
        __syncthreads();
        if (c + 2 < INKC) load_stage(st, c + 2);
    }

    // Output in two 64-col halves (warps with wn==h own half h).
#pragma unroll
    for (int h = 0; h < 2; h++) {
        __syncthreads();
        if (wn == h) {
#pragma unroll
            for (int i = 0; i < 2; i++)
#pragma unroll
                for (int j = 0; j < 4; j++)
                    wmma::store_matrix_sync(Ps + (size_t)(wm * 32 + i * 16) * IPSP + j * 16,
                                            acc[i][j], IPSP, wmma::mem_row_major);
        }
        __syncthreads();

        int nb = n0 + h * 64;
        int g = nb >> 10;
        int ub = nb & 1023;
#pragma unroll
        for (int i = 0; i < 8; i++) {
            int lin = tid + i * 256;          // 0..2047
            int row = lin >> 4;               // 0..127
            int q   = lin & 15;               // float4 within 64 cols
            float4 v = *(const float4*)&Ps[row * IPSP + q * 4];
            float4 bv = *(const float4*)&bias0[nb + q * 4];
            v.x += bv.x; v.y += bv.y; v.z += bv.z; v.w += bv.w;
            int m = m0 + row;
            int b = m >> 9, t = m & 511;
            *(float4*)&g_xp[(((size_t)g * TT + t) * BB + b) * UU + ub + q * 4] = v;
        }
    }
}

// ---------------------------------------------------------------------------
// Persistent WMMA GRU scan (R13 config, B ring reduced to 2 chunks of 256).
// 144 CTAs x 256 threads; A slice smem-resident; staging aliases B buffer 0;
// single atomic barrier; register h; fast-intrinsic epilogue.
// ---------------------------------------------------------------------------
__global__ void __launch_bounds__(256, 1)
gru_wmma_kernel(const float* __restrict__ hidden0,
                const float* __restrict__ bias,
                float* __restrict__ out,
                int write_state) {
    extern __shared__ unsigned char sm[];
    __nv_bfloat16* Asm = (__nv_bfloat16*)sm;
    unsigned char* Bsm = sm + A_BYTES;
    float* Ps = (float*)Bsm;                 // staging aliases B buffer 0 (33792 B)

    int tid = threadIdx.x;
    int cta = blockIdx.x;
    int mt = cta / NSL;
    int s  = cta - mt * NSL;
    int w  = tid >> 5;
    int wm = w & 3;          // m-group (32 rows)
    int wn = w >> 2;         // n-group (32 cols)

    // Load resident A slice once.
    {
        const unsigned char* src = (const unsigned char*)g_Apack + (size_t)cta * A_BYTES;
        for (int i = tid; i < A_BYTES / 16; i += 256)
            cp16(sm + (size_t)i * 16, src + (size_t)i * 16);
        cpa_commit();
        asm volatile("cp.async.wait_group 0;\n");
    }
    __syncthreads();

    int kbase = s * KSL;     // column window in Bcat
    int brow = tid >> 2;     // 0..63 (B row per thread)
    int bq   = tid & 3;

    // Epilogue unit (float2, static for all steps).
    int unit = cta * UPC2 + tid;
    bool edo = (tid < UPC2) && (unit < NU2);
    int eb = 0, eu2 = 0;
    float bzv[2] = {0,0}, brv[2] = {0,0}, bhv[2] = {0,0};
    float hpv[2] = {0,0};
    if (edo) {
        eb  = unit >> 9;
        eu2 = (unit & 511) << 1;
        float2 t2;
        t2 = *(const float2*)&bias[G3 + eu2];           bzv[0]=t2.x; bzv[1]=t2.y;
        t2 = *(const float2*)&bias[G3 + UU + eu2];      brv[0]=t2.x; brv[1]=t2.y;
        t2 = *(const float2*)&bias[G3 + 2 * UU + eu2];  bhv[0]=t2.x; bhv[1]=t2.y;
        t2 = *(const float2*)&hidden0[(size_t)eb * UU + eu2];
        hpv[0]=t2.x; hpv[1]=t2.y;
    }

    const __nv_bfloat16* Aw = Asm + (size_t)(wm * 32) * A_PITCH;
    float* gpp = g_Pp + ((size_t)s * BB) * G3 + mt * 128;   // + b*G3 + m

    unsigned tgt = 0;
    for (int t = 0; t < TT; t++) {
        // Issue both 256-col B chunks (2 commit groups).
#pragma unroll
        for (int kc = 0; kc < 2; kc++) {
            const unsigned char* srow = (const unsigned char*)
                (g_Bcat + (size_t)brow * G3 + kbase + kc * 256) + bq * 16;
            unsigned char* drow = Bsm + kc * BCH_BYTES + brow * (B_PITCH * 2) + bq * 16;
#pragma unroll
            for (int i = 0; i < 8; i++) cp16(drow + i * 64, srow + i * 64);
            cpa_commit();
        }

        wmma::fragment<wmma::accumulator, 16, 16, 16, float> acc[2][2];
#pragma unroll
        for (int i = 0; i < 2; i++)
#pragma unroll
            for (int j = 0; j < 2; j++) wmma::fill_fragment(acc[i][j], 0.0f);

#pragma unroll
        for (int kc = 0; kc < 2; kc++) {
            if (kc == 0) asm volatile("cp.async.wait_group 1;\n");
            else         asm volatile("cp.async.wait_group 0;\n");
            __syncthreads();

            const __nv_bfloat16* Bb = (const __nv_bfloat16*)(Bsm + kc * BCH_BYTES);
#pragma unroll
            for (int kk = 0; kk < 16; kk++) {
                int kof = kc * 256 + kk * 16;
                wmma::fragment<wmma::matrix_a, 16, 16, 16, __nv_bfloat16, wmma::row_major> af[2];
                wmma::fragment<wmma::matrix_b, 16, 16, 16, __nv_bfloat16, wmma::col_major> bf[2];
                wmma::load_matrix_sync(af[0], Aw + kof, A_PITCH);
                wmma::load_matrix_sync(af[1], Aw + (size_t)16 * A_PITCH + kof, A_PITCH);
                wmma::load_matrix_sync(bf[0], Bb + (size_t)(wn * 32) * B_PITCH + kk * 16, B_PITCH);
                wmma::load_matrix_sync(bf[1], Bb + (size_t)(wn * 32 + 16) * B_PITCH + kk * 16, B_PITCH);
                wmma::mma_sync(acc[0][0], af[0], bf[0], acc[0][0]);
                wmma::mma_sync(acc[0][1], af[0], bf[1], acc[0][1]);
                wmma::mma_sync(acc[1][0], af[1], bf[0], acc[1][0]);
                wmma::mma_sync(acc[1][1], af[1], bf[1], acc[1][1]);
            }
        }

        // Stage partials in smem (col-major). Safe aliasing: all warps passed
        // the kc=1 sync, so B buffer 0 is no longer read; staging fits buf 0.
#pragma unroll
        for (int i = 0; i < 2; i++)
#pragma unroll
            for (int j = 0; j < 2; j++)
                wmma::store_matrix_sync(Ps + (wm * 32 + i * 16) + (size_t)(wn * 32 + j * 16) * PS_LD,
                                        acc[i][j], PS_LD, wmma::mem_col_major);

        // Prefetch xp — hides under staging + bar1.
        float xzv[2], xrv[2], xhv[2];
        if (edo) {
            float2 xz = *(const float2*)&g_xp[(((size_t)0 * TT + t) * BB + eb) * UU + eu2];
            float2 xr = *(const float2*)&g_xp[(((size_t)1 * TT + t) * BB + eb) * UU + eu2];
            float2 xh = *(const float2*)&g_xp[(((size_t)2 * TT + t) * BB + eb) * UU + eu2];
            xzv[0]=xz.x; xzv[1]=xz.y;
            xrv[0]=xr.x; xrv[1]=xr.y;
            xhv[0]=xh.x; xhv[1]=xh.y;
        }
        __syncthreads();

        // Coalesced copy staging -> g_Pp[s][b][mt*128 + m] (512B runs).
#pragma unroll
        for (int i = 0; i < 8; i++) {
            int lin = tid + i * 256;          // 0..2047
            int b = lin >> 5;
            int q = lin & 31;                 // float4 index within 128-float row
            float4 v = *(const float4*)&Ps[q * 4 + b * PS_LD];
            *(float4*)&gpp[(size_t)b * G3 + q * 4] = v;
        }

        tgt += NCTA; gbar_sync(tgt);

        // Distributed epilogue: one float2 unit (eb, eu2..eu2+1) per thread.
        if (edo) {
            float sz[2] = {0, 0}, sr[2] = {0, 0}, sh[2] = {0, 0};
#pragma unroll
            for (int si = 0; si < NSL; si++) {
                const float* pb = g_Pp + ((size_t)si * BB + eb) * G3;
                float2 vz = __ldcg((const float2*)(pb + eu2));
                float2 vr = __ldcg((const float2*)(pb + 1024 + eu2));
                float2 vh = __ldcg((const float2*)(pb + 2048 + eu2));
                sz[0] += vz.x; sz[1] += vz.y;
                sr[0] += vr.x; sr[1] += vr.y;
                sh[0] += vh.x; sh[1] += vh.y;
            }
            float hn[2], lo[2];
#pragma unroll
            for (int j = 0; j < 2; j++) {
                float z  = __fdividef(1.f, 1.f + __expf(-(xzv[j] + sz[j] + bzv[j])));
                float rg = __fdividef(1.f, 1.f + __expf(-(xrv[j] + sr[j] + brv[j])));
                float ta = xhv[j] + rg * (sh[j] + bhv[j]);
                float hh = 1.f - __fdividef(2.f, __expf(2.f * ta) + 1.f);
                hn[j] = z * hpv[j] + (1.f - z) * hh;
                hpv[j] = hn[j];                       // h_prev stays in registers
                __nv_bfloat16 hi = __float2bfloat16(hn[j]);
                lo[j] = hn[j] - __bfloat162float(hi);
            }
            // Bcat stores first (bar2 + next-step GEMM wait on these).
            unsigned hv = packbf2(hn[0], hn[1]);
            unsigned lv = packbf2(lo[0], lo[1]);
            *(unsigned*)&g_Bcat[(size_t)eb * G3 + eu2] = hv;
            *(unsigned*)&g_Bcat[(size_t)eb * G3 + 1024 + eu2] = lv;
            *(unsigned*)&g_Bcat[(size_t)eb * G3 + 2048 + eu2] = hv;
            *(float2*)&out[((size_t)eb * TT + t) * UU + eu2] = make_float2(hn[0], hn[1]);
            if (write_state && t == TT - 1)
                *(float2*)&out[(size_t)BB * TT * UU + (size_t)eb * UU + eu2] =
                    make_float2(hn[0], hn[1]);
        }

        tgt += NCTA; gbar_sync(tgt);
    }
}

// ---------------------------------------------------------------------------
extern "C" void kernel_launch(void* const* d_in, const int* in_sizes, int n_in,
                              void* d_out, int out_size) {
    const int*   x      = (const int*)d_in[0];
    const float* hidden = (const float*)d_in[1];
    const float* emb    = (const float*)d_in[2];
    const float* W      = (const float*)d_in[3];
    const float* Rk     = (const float*)d_in[4];
    const float* bias   = (const float*)d_in[5];
    float* out = (float*)d_out;

    int write_state = (out_size >= BB * TT * UU + BB * UU) ? 1 : 0;

    static int attr_done = 0;
    if (!attr_done) {
        cudaFuncSetAttribute(gru_wmma_kernel,
                             cudaFuncAttributeMaxDynamicSharedMemorySize, SMEM_BYTES);
        attr_done = 1;
    }

    init_bar_kernel<<<1, 1>>>();

    size_t ae = (size_t)G3 * G3;
    pack_A_kernel<<<(unsigned)((ae + 255) / 256), 256>>>(Rk);
    prep_B_kernel<<<(BB * UU + 255) / 256, 256>>>(hidden);

    size_t we = (size_t)IKP * G3;
    pack_W_kernel<<<(unsigned)((we + 255) / 256), 256>>>(W);
    pack_Acat_kernel<<<(BB * TT) / 8, 256>>>(x, emb);

    dim3 gI(G3 / 128, (BB * TT) / 128);   // (24, 256)
    input_wmma_kernel<<<gI, 256>>>(bias);

    gru_wmma_kernel<<<NCTA, 256, SMEM_BYTES>>>(hidden, bias, out, write_state);
}

// round 17
// speedup vs baseline: 1.1722x; 1.0111x over previous
#include <cuda_runtime.h>
#include <cuda_bf16.h>
#include <mma.h>
#include <cstdint>
#include <cstddef>

using namespace nvcuda;

#define BB 64
#define TT 512
#define EE 300
#define UU 1024
#define G3 3072
#define NCTA 144           // 24 m-tiles x 6 k-slices
#define NSL 6
#define KSL 512
#define A_PITCH 520        // 512 + 8 pad (conflict-free ldmatrix)
#define A_BYTES (128 * A_PITCH * 2)       // 133120
#define B_PITCH 264        // 256 + 8 pad (bf16 elements)
#define BCH_BYTES (64 * B_PITCH * 2)      // 33792
#define PS_LD 132                         // staging ldm (col-major, 128 rows + pad)
#define SMEM_BYTES (A_BYTES + 2 * BCH_BYTES)                 // 200704
#define NU2 (BB * (UU / 2))               // 32768 float2 epilogue units
#define UPC2 228                          // ceil(NU2 / NCTA)

// Input-GEMM (bf16-split WMMA) geometry — 128x128 tile
#define IEK 304            // padded E per region
#define IKP (3 * IEK)      // K' = 912
#define IKC 48             // K chunk
#define INKC (IKP / IKC)   // 19 chunks
#define IAP 56             // A smem pitch (bf16)
#define IBP 136            // B smem pitch (bf16), 128 + 8
#define IPSP 72            // output staging pitch (float), 64 cols + 8

// ---- static device scratch ----
__device__ float g_xp[(size_t)3 * TT * BB * UU];                     // [gate][t][b][u]
__device__ __align__(16) __nv_bfloat16 g_Apack[(size_t)NCTA * 128 * A_PITCH];
__device__ __align__(16) __nv_bfloat16 g_Bcat[(size_t)BB * G3];      // [b][hhi|hlo|hhi]
__device__ float g_Pp[(size_t)NSL * BB * G3];                        // [slice][b][m]
__device__ __align__(16) __nv_bfloat16 g_Acat[(size_t)BB * TT * IKP];  // gathered emb split
__device__ __align__(16) __nv_bfloat16 g_Wcat[(size_t)IKP * G3];       // kernel split
__device__ unsigned g_bar;

__global__ void init_bar_kernel() { g_bar = 0u; }

__device__ __forceinline__ void cp16(void* dst, const void* src) {
    unsigned d = (unsigned)__cvta_generic_to_shared(dst);
    asm volatile("cp.async.cg.shared.global [%0], [%1], 16;\n" :: "r"(d), "l"(src));
}
__device__ __forceinline__ void cpa_commit() {
    asm volatile("cp.async.commit_group;\n");
}
__device__ __forceinline__ unsigned packbf2(float a, float b) {
    __nv_bfloat16 ha = __float2bfloat16(a), hb = __float2bfloat16(b);
    unsigned short ua = *(unsigned short*)&ha, ub = *(unsigned short*)&hb;
    return (unsigned)ua | ((unsigned)ub << 16);
}

// Proven atomic-counter grid barrier.
__device__ __forceinline__ void gbar_sync(unsigned target) {
    __syncthreads();
    if (threadIdx.x == 0) {
        __threadfence();
        atomicAdd(&g_bar, 1u);
        while (*(volatile unsigned*)&g_bar < target) { }
        __threadfence();
    }
    __syncthreads();
}

// ---------------------------------------------------------------------------
// Pack A' via 32x32 smem transpose. Grid (96, 32): m0 = bx*32, k0 = by*32.
// R[k][m] feeds three slices: s=k>>9 (hi), s=2+(k>>9) (hi), s=4+(k>>9) (lo);
// dest: g_Apack[(mt*6 + s)*(128*A_PITCH) + (m&127)*A_PITCH + (k&511)].
// ---------------------------------------------------------------------------
__global__ void pack_A_kernel(const float* __restrict__ Rk) {
    __shared__ float tile[32][33];
    int m0 = blockIdx.x * 32;
    int k0 = blockIdx.y * 32;
    int tx = threadIdx.x & 31;
    int ty = threadIdx.x >> 5;            // 0..7

    // Coalesced load: rows k0+ty+8i, cols m0+tx.
#pragma unroll
    for (int i = 0; i < 4; i++)
        tile[ty + 8 * i][tx] = Rk[(size_t)(k0 + ty + 8 * i) * G3 + (m0 + tx)];
    __syncthreads();

    // Transposed write: thread covers k = k0+tx (consecutive j), m = m0+ty+8i.
#pragma unroll
    for (int i = 0; i < 4; i++) {
        int m = m0 + ty + 8 * i;
        int k = k0 + tx;
        float v = tile[tx][ty + 8 * i];
        __nv_bfloat16 hi = __float2bfloat16(v);
        __nv_bfloat16 lo = __float2bfloat16(v - __bfloat162float(hi));
        int mt = m >> 7, ml = m & 127;
        size_t base = (size_t)mt * NSL * (128 * A_PITCH) + (size_t)ml * A_PITCH + (k & 511);
        size_t soff = (size_t)(k >> 9) * (128 * A_PITCH);
        g_Apack[base + soff] = hi;                                   // kp = k
        g_Apack[base + soff + (size_t)2 * (128 * A_PITCH)] = hi;     // kp = 1024+k
        g_Apack[base + soff + (size_t)4 * (128 * A_PITCH)] = lo;     // kp = 2048+k
    }
}

// ---------------------------------------------------------------------------
__global__ void prep_B_kernel(const float* __restrict__ hidden0) {
    int idx = blockIdx.x * 256 + threadIdx.x;
    if (idx >= BB * UU) return;
    int b = idx >> 10, u = idx & 1023;
    float v = hidden0[idx];
    __nv_bfloat16 hi = __float2bfloat16(v);
    __nv_bfloat16 lo = __float2bfloat16(v - __bfloat162float(hi));
    g_Bcat[(size_t)b * G3 + u] = hi;
    g_Bcat[(size_t)b * G3 + 1024 + u] = lo;
    g_Bcat[(size_t)b * G3 + 2048 + u] = hi;
}

// ---------------------------------------------------------------------------
__global__ void pack_W_kernel(const float* __restrict__ W) {
    size_t idx = (size_t)blockIdx.x * 256 + threadIdx.x;
    if (idx >= (size_t)IKP * G3) return;
    int kp = (int)(idx / G3);
    int n  = (int)(idx - (size_t)kp * G3);
    int region = (kp >= 2 * IEK) ? 2 : (kp >= IEK ? 1 : 0);
    int e = kp - region * IEK;
    float v = (e < EE) ? W[(size_t)e * G3 + n] : 0.f;
    __nv_bfloat16 hi = __float2bfloat16(v);
    __nv_bfloat16 wv = (region == 2) ? __float2bfloat16(v - __bfloat162float(hi)) : hi;
    g_Wcat[idx] = wv;
}

__global__ void pack_Acat_kernel(const int* __restrict__ x,
                                 const float* __restrict__ emb) {
    int m = blockIdx.x * 8 + (threadIdx.x >> 5);
    int lane = threadIdx.x & 31;
    int tok = x[m];
    const float* erow = emb + (size_t)tok * EE;
    __nv_bfloat16* arow = g_Acat + (size_t)m * IKP;
    for (int c = lane; c < IEK; c += 32) {
        float v = (c < EE) ? erow[c] : 0.f;
        __nv_bfloat16 hi = __float2bfloat16(v);
        __nv_bfloat16 lo = __float2bfloat16(v - __bfloat162float(hi));
        arow[c] = hi;
        arow[IEK + c] = lo;
        arow[2 * IEK + c] = hi;
    }
}

// ---------------------------------------------------------------------------
// Input GEMM (WMMA bf16-split), 128m x 128n tile, 8 warps (32m x 64n each),
// K chunks of 48, 2-stage cp.async. Output staged per 64-col half.
// ---------------------------------------------------------------------------
__global__ void __launch_bounds__(256, 2)
input_wmma_kernel(const float* __restrict__ bias0) {
    __shared__ __align__(16) unsigned char smbuf[2 * 128 * IAP * 2 + 2 * IKC * IBP * 2];
    __nv_bfloat16* Asm = (__nv_bfloat16*)smbuf;                       // [2][128*IAP]
    __nv_bfloat16* Bsm = (__nv_bfloat16*)(smbuf + 2 * 128 * IAP * 2); // [2][IKC*IBP]
    float* Ps = (float*)smbuf;   // alias after GEMM

    int tid = threadIdx.x;
    int n0 = blockIdx.x * 128;
    int m0 = blockIdx.y * 128;
    int w  = tid >> 5;
    int wm = w & 3;           // 32-row group
    int wn = w >> 2;          // 64-col group (0..1)

    auto load_stage = [&](int st, int c) {
        int k0 = c * IKC;
#pragma unroll
        for (int i = 0; i < 3; i++) {             // A: 768 x 16B
            int lin = tid + i * 256;
            int row = lin / 6, seg = lin % 6;
            cp16(Asm + (size_t)st * 128 * IAP + row * IAP + seg * 8,
                 g_Acat + (size_t)(m0 + row) * IKP + k0 + seg * 8);
        }
#pragma unroll
        for (int i = 0; i < 3; i++) {             // B: 48x128 = 768 x 16B
            int lin = tid + i * 256;
            int row = lin >> 4, seg = lin & 15;
            cp16(Bsm + (size_t)st * IKC * IBP + row * IBP + seg * 8,
                 g_Wcat + (size_t)(k0 + row) * G3 + n0 + seg * 8);
        }
        cpa_commit();
    };

    load_stage(0, 0);
    load_stage(1, 1);

    wmma::fragment<wmma::accumulator, 16, 16, 16, float> acc[2][4];
#pragma unroll
    for (int i = 0; i < 2; i++)
#pragma unroll
        for (int j = 0; j < 4; j++) wmma::fill_fragment(acc[i][j], 0.0f);

    for (int c = 0; c < INKC; c++) {
        if (c + 1 < INKC) asm volatile("cp.async.wait_group 1;\n");
        else              asm volatile("cp.async.wait_group 0;\n");
        __syncthreads();

        int st = c & 1;
        const __nv_bfloat16* Ab = Asm + (size_t)st * 128 * IAP + (size_t)(wm * 32) * IAP;
        const __nv_bfloat16* Bb = Bsm + (size_t)st * IKC * IBP + wn * 64;
#pragma unroll
        for (int kk = 0; kk < 3; kk++) {
            wmma::fragment<wmma::matrix_a, 16, 16, 16, __nv_bfloat16, wmma::row_major> af[2];
            wmma::fragment<wmma::matrix_b, 16, 16, 16, __nv_bfloat16, wmma::row_major> bf[4];
            wmma::load_matrix_sync(af[0], Ab + kk * 16, IAP);
            wmma::load_matrix_sync(af[1], Ab + (size_t)16 * IAP + kk * 16, IAP);
#pragma unroll
            for (int j = 0; j < 4; j++)
                wmma::load_matrix_sync(bf[j], Bb + (size_t)(kk * 16) * IBP + j * 16, IBP);
#pragma unroll
            for (int j = 0; j < 4; j++) {
                wmma::mma_sync(acc[0][j], af[0], bf[j], acc[0][j]);
                wmma::mma_sync(acc[1][j], af[1], bf[j], acc[1][j]);
            }
        }
        __syncthreads();
        if (c + 2 < INKC) load_stage(st, c + 2);
    }

    // Output in two 64-col halves (warps with wn==h own half h).
#pragma unroll
    for (int h = 0; h < 2; h++) {
        __syncthreads();
        if (wn == h) {
#pragma unroll
            for (int i = 0; i < 2; i++)
#pragma unroll
                for (int j = 0; j < 4; j++)
                    wmma::store_matrix_sync(Ps + (size_t)(wm * 32 + i * 16) * IPSP + j * 16,
                                            acc[i][j], IPSP, wmma::mem_row_major);
        }
        __syncthreads();

        int nb = n0 + h * 64;
        int g = nb >> 10;
        int ub = nb & 1023;
#pragma unroll
        for (int i = 0; i < 8; i++) {
            int lin = tid + i * 256;          // 0..2047
            int row = lin >> 4;               // 0..127
            int q   = lin & 15;               // float4 within 64 cols
            float4 v = *(const float4*)&Ps[row * IPSP + q * 4];
            float4 bv = *(const float4*)&bias0[nb + q * 4];
            v.x += bv.x; v.y += bv.y; v.z += bv.z; v.w += bv.w;
            int m = m0 + row;
            int b = m >> 9, t = m & 511;
            *(float4*)&g_xp[(((size_t)g * TT + t) * BB + b) * UU + ub + q * 4] = v;
        }
    }
}

// ---------------------------------------------------------------------------
// Persistent WMMA GRU scan (R15 config: 256 thr, 8 warps, 2-chunk B ring of
// 256 cols, staging aliases B buffer 0, single atomic barrier, register h,
// fast-intrinsic epilogue with fma form).
// ---------------------------------------------------------------------------
__global__ void __launch_bounds__(256, 1)
gru_wmma_kernel(const float* __restrict__ hidden0,
                const float* __restrict__ bias,
                float* __restrict__ out,
                int write_state) {
    extern __shared__ unsigned char sm[];
    __nv_bfloat16* Asm = (__nv_bfloat16*)sm;
    unsigned char* Bsm = sm + A_BYTES;
    float* Ps = (float*)Bsm;                 // staging aliases B buffer 0 (33792 B)

    int tid = threadIdx.x;
    int cta = blockIdx.x;
    int mt = cta / NSL;
    int s  = cta - mt * NSL;
    int w  = tid >> 5;
    int wm = w & 3;          // m-group (32 rows)
    int wn = w >> 2;         // n-group (32 cols)

    // Load resident A slice once.
    {
        const unsigned char* src = (const unsigned char*)g_Apack + (size_t)cta * A_BYTES;
        for (int i = tid; i < A_BYTES / 16; i += 256)
            cp16(sm + (size_t)i * 16, src + (size_t)i * 16);
        cpa_commit();
        asm volatile("cp.async.wait_group 0;\n");
    }
    __syncthreads();

    int kbase = s * KSL;     // column window in Bcat
    int brow = tid >> 2;     // 0..63 (B row per thread)
    int bq   = tid & 3;

    // Epilogue unit (float2, static for all steps).
    int unit = cta * UPC2 + tid;
    bool edo = (tid < UPC2) && (unit < NU2);
    int eb = 0, eu2 = 0;
    float bzv[2] = {0,0}, brv[2] = {0,0}, bhv[2] = {0,0};
    float hpv[2] = {0,0};
    if (edo) {
        eb  = unit >> 9;
        eu2 = (unit & 511) << 1;
        float2 t2;
        t2 = *(const float2*)&bias[G3 + eu2];           bzv[0]=t2.x; bzv[1]=t2.y;
        t2 = *(const float2*)&bias[G3 + UU + eu2];      brv[0]=t2.x; brv[1]=t2.y;
        t2 = *(const float2*)&bias[G3 + 2 * UU + eu2];  bhv[0]=t2.x; bhv[1]=t2.y;
        t2 = *(const float2*)&hidden0[(size_t)eb * UU + eu2];
        hpv[0]=t2.x; hpv[1]=t2.y;
    }

    const __nv_bfloat16* Aw = Asm + (size_t)(wm * 32) * A_PITCH;
    float* gpp = g_Pp + ((size_t)s * BB) * G3 + mt * 128;   // + b*G3 + m

    unsigned tgt = 0;
    for (int t = 0; t < TT; t++) {
        // Issue both 256-col B chunks (2 commit groups).
#pragma unroll
        for (int kc = 0; kc < 2; kc++) {
            const unsigned char* srow = (const unsigned char*)
                (g_Bcat + (size_t)brow * G3 + kbase + kc * 256) + bq * 16;
            unsigned char* drow = Bsm + kc * BCH_BYTES + brow * (B_PITCH * 2) + bq * 16;
#pragma unroll
            for (int i = 0; i < 8; i++) cp16(drow + i * 64, srow + i * 64);
            cpa_commit();
        }

        wmma::fragment<wmma::accumulator, 16, 16, 16, float> acc[2][2];
#pragma unroll
        for (int i = 0; i < 2; i++)
#pragma unroll
            for (int j = 0; j < 2; j++) wmma::fill_fragment(acc[i][j], 0.0f);

#pragma unroll
        for (int kc = 0; kc < 2; kc++) {
            if (kc == 0) asm volatile("cp.async.wait_group 1;\n");
            else         asm volatile("cp.async.wait_group 0;\n");
            __syncthreads();

            const __nv_bfloat16* Bb = (const __nv_bfloat16*)(Bsm + kc * BCH_BYTES);
#pragma unroll
            for (int kk = 0; kk < 16; kk++) {
                int kof = kc * 256 + kk * 16;
                wmma::fragment<wmma::matrix_a, 16, 16, 16, __nv_bfloat16, wmma::row_major> af[2];
                wmma::fragment<wmma::matrix_b, 16, 16, 16, __nv_bfloat16, wmma::col_major> bf[2];
                wmma::load_matrix_sync(af[0], Aw + kof, A_PITCH);
                wmma::load_matrix_sync(af[1], Aw + (size_t)16 * A_PITCH + kof, A_PITCH);
                wmma::load_matrix_sync(bf[0], Bb + (size_t)(wn * 32) * B_PITCH + kk * 16, B_PITCH);
                wmma::load_matrix_sync(bf[1], Bb + (size_t)(wn * 32 + 16) * B_PITCH + kk * 16, B_PITCH);
                wmma::mma_sync(acc[0][0], af[0], bf[0], acc[0][0]);
                wmma::mma_sync(acc[0][1], af[0], bf[1], acc[0][1]);
                wmma::mma_sync(acc[1][0], af[1], bf[0], acc[1][0]);
                wmma::mma_sync(acc[1][1], af[1], bf[1], acc[1][1]);
            }
        }

        // Stage partials in smem (col-major). Safe aliasing: all warps passed
        // the kc=1 sync, so B buffer 0 is no longer read; staging fits buf 0.
#pragma unroll
        for (int i = 0; i < 2; i++)
#pragma unroll
            for (int j = 0; j < 2; j++)
                wmma::store_matrix_sync(Ps + (wm * 32 + i * 16) + (size_t)(wn * 32 + j * 16) * PS_LD,
                                        acc[i][j], PS_LD, wmma::mem_col_major);

        // Prefetch xp — hides under staging + bar1.
        float xzv[2], xrv[2], xhv[2];
        if (edo) {
            float2 xz = *(const float2*)&g_xp[(((size_t)0 * TT + t) * BB + eb) * UU + eu2];
            float2 xr = *(const float2*)&g_xp[(((size_t)1 * TT + t) * BB + eb) * UU + eu2];
            float2 xh = *(const float2*)&g_xp[(((size_t)2 * TT + t) * BB + eb) * UU + eu2];
            xzv[0]=xz.x; xzv[1]=xz.y;
            xrv[0]=xr.x; xrv[1]=xr.y;
            xhv[0]=xh.x; xhv[1]=xh.y;
        }
        __syncthreads();

        // Coalesced copy staging -> g_Pp[s][b][mt*128 + m] (512B runs).
#pragma unroll
        for (int i = 0; i < 8; i++) {
            int lin = tid + i * 256;          // 0..2047
            int b = lin >> 5;
            int q = lin & 31;                 // float4 index within 128-float row
            float4 v = *(const float4*)&Ps[q * 4 + b * PS_LD];
            *(float4*)&gpp[(size_t)b * G3 + q * 4] = v;
        }

        tgt += NCTA; gbar_sync(tgt);

        // Distributed epilogue: one float2 unit (eb, eu2..eu2+1) per thread.
        if (edo) {
            float sz[2] = {0, 0}, sr[2] = {0, 0}, sh[2] = {0, 0};
#pragma unroll
            for (int si = 0; si < NSL; si++) {
                const float* pb = g_Pp + ((size_t)si * BB + eb) * G3;
                float2 vz = __ldcg((const float2*)(pb + eu2));
                float2 vr = __ldcg((const float2*)(pb + 1024 + eu2));
                float2 vh = __ldcg((const float2*)(pb + 2048 + eu2));
                sz[0] += vz.x; sz[1] += vz.y;
                sr[0] += vr.x; sr[1] += vr.y;
                sh[0] += vh.x; sh[1] += vh.y;
            }
            float hn[2], lo[2];
#pragma unroll
            for (int j = 0; j < 2; j++) {
                float z  = __fdividef(1.f, 1.f + __expf(-(xzv[j] + sz[j] + bzv[j])));
                float rg = __fdividef(1.f, 1.f + __expf(-(xrv[j] + sr[j] + brv[j])));
                float ta = xhv[j] + rg * (sh[j] + bhv[j]);
                float hh = 1.f - __fdividef(2.f, __expf(2.f * ta) + 1.f);
                hn[j] = fmaf(z, hpv[j] - hh, hh);     // z*hp + (1-z)*hh
                hpv[j] = hn[j];                       // h_prev stays in registers
                __nv_bfloat16 hi = __float2bfloat16(hn[j]);
                lo[j] = hn[j] - __bfloat162float(hi);
            }
            // Bcat stores first (bar2 + next-step GEMM wait on these).
            unsigned hv = packbf2(hn[0], hn[1]);
            unsigned lv = packbf2(lo[0], lo[1]);
            *(unsigned*)&g_Bcat[(size_t)eb * G3 + eu2] = hv;
            *(unsigned*)&g_Bcat[(size_t)eb * G3 + 1024 + eu2] = lv;
            *(unsigned*)&g_Bcat[(size_t)eb * G3 + 2048 + eu2] = hv;
            *(float2*)&out[((size_t)eb * TT + t) * UU + eu2] = make_float2(hn[0], hn[1]);
            if (write_state && t == TT - 1)
                *(float2*)&out[(size_t)BB * TT * UU + (size_t)eb * UU + eu2] =
                    make_float2(hn[0], hn[1]);
        }

        tgt += NCTA; gbar_sync(tgt);
    }
}

// ---------------------------------------------------------------------------
extern "C" void kernel_launch(void* const* d_in, const int* in_sizes, int n_in,
                              void* d_out, int out_size) {
    const int*   x      = (const int*)d_in[0];
    const float* hidden = (const float*)d_in[1];
    const float* emb    = (const float*)d_in[2];
    const float* W      = (const float*)d_in[3];
    const float* Rk     = (const float*)d_in[4];
    const float* bias   = (const float*)d_in[5];
    float* out = (float*)d_out;

    int write_state = (out_size >= BB * TT * UU + BB * UU) ? 1 : 0;

    static int attr_done = 0;
    if (!attr_done) {
        cudaFuncSetAttribute(gru_wmma_kernel,
                             cudaFuncAttributeMaxDynamicSharedMemorySize, SMEM_BYTES);
        attr_done = 1;
    }

    init_bar_kernel<<<1, 1>>>();

    dim3 gP(96, 32);                         // m-tiles x k-tiles, no modulo
    pack_A_kernel<<<gP, 256>>>(Rk);
    prep_B_kernel<<<(BB * UU + 255) / 256, 256>>>(hidden);

    size_t we = (size_t)IKP * G3;
    pack_W_kernel<<<(unsigned)((we + 255) / 256), 256>>>(W);
    pack_Acat_kernel<<<(BB * TT) / 8, 256>>>(x, emb);

    dim3 gI(G3 / 128, (BB * TT) / 128);   // (24, 256)
    input_wmma_kernel<<<gI, 256>>>(bias);

    gru_wmma_kernel<<<NCTA, 256, SMEM_BYTES>>>(hidden, bias, out, write_state);
}